// round 8
// baseline (speedup 1.0000x reference)
#include <cuda_runtime.h>
#include <cuda_bf16.h>
#include <math.h>

// ---------------------------------------------------------------------------
// SlotAttentionMulti — factored, bf16 xn, fused attention + fused slot chain.
//   xnb = bf16(LN(x));  M_comb = coef*W_qry@W_k^T;  M_vih = W_v@w_ih^T; w_hhT
//   per step:
//     fused_pre : build slots + LN(q) + qproj + gh          (64 blocks)
//     attn_fused: logits + slot softmax + rowsum + upart    (2048 blocks)
//     fused_post: ureduce + gi + GRU + LN + MLP + sview     (64 blocks)
//     means_attr: slot_attr means                            (96 blocks)
// ---------------------------------------------------------------------------

#define BVDIM 64
#define NTOK  4096
#define NS    8
#define SVD   64
#define SAD   192
#define ROWS  512
#define NCHUNK 32
#define CHUNK 128
#define COEF  0.08838834764831843f

// ------------------------------ device scratch -----------------------------
__device__ __nv_bfloat16 g_xnb[(size_t)BVDIM * NTOK * 256];
__device__ float g_upart[(size_t)NCHUNK * ROWS * 256];
__device__ float g_rspart[NCHUNK * ROWS];
__device__ float g_qproj[ROWS * 256];
__device__ float g_h[ROWS * 256];
__device__ float g_gh[ROWS * 768];
__device__ float g_snew[ROWS * 256];
__device__ float g_sview[BVDIM * SVD];
__device__ float g_sattr[16 * NS * SAD];
__device__ float g_Mcomb[256 * 256];
__device__ float g_Mvih[256 * 768];
__device__ float g_whhT[256 * 768];

// ------------------------------ helpers ------------------------------------
__device__ __forceinline__ float sigmoidf(float x) { return 1.f / (1.f + expf(-x)); }

__device__ __forceinline__ unsigned long long pack2(float lo, float hi) {
    unsigned long long r;
    asm("mov.b64 %0, {%1, %2};" : "=l"(r) : "f"(lo), "f"(hi));
    return r;
}
__device__ __forceinline__ void ffma2(unsigned long long& acc,
                                      unsigned long long a, unsigned long long b) {
    asm("fma.rn.f32x2 %0, %1, %2, %0;" : "+l"(acc) : "l"(a), "l"(b));
}
__device__ __forceinline__ float2 unpack2(unsigned long long v) {
    float2 r;
    asm("mov.b64 {%0, %1}, %2;" : "=f"(r.x), "=f"(r.y) : "l"(v));
    return r;
}

// ------------------------------ LN over x -> bf16 --------------------------
__global__ void __launch_bounds__(256) ln_x_kernel(
    const float* __restrict__ x, const float* __restrict__ g, const float* __restrict__ b)
{
    int w = threadIdx.x >> 5, lane = threadIdx.x & 31;
    size_t row = (size_t)blockIdx.x * 8 + w;
    const float4* xr = (const float4*)(x + row * 256);
    float4 v0 = xr[lane], v1 = xr[lane + 32];
    float s = v0.x + v0.y + v0.z + v0.w + v1.x + v1.y + v1.z + v1.w;
    float ss = v0.x*v0.x + v0.y*v0.y + v0.z*v0.z + v0.w*v0.w
             + v1.x*v1.x + v1.y*v1.y + v1.z*v1.z + v1.w*v1.w;
    #pragma unroll
    for (int o = 16; o; o >>= 1) {
        s  += __shfl_xor_sync(0xffffffffu, s, o);
        ss += __shfl_xor_sync(0xffffffffu, ss, o);
    }
    float mu = s * (1.f / 256.f);
    float var = ss * (1.f / 256.f) - mu * mu;
    float rs = rsqrtf(var + 1e-5f);
    const float4* g4 = (const float4*)g;
    const float4* b4 = (const float4*)b;
    float4 G0 = g4[lane], G1 = g4[lane + 32], B0 = b4[lane], B1 = b4[lane + 32];
    __nv_bfloat162 p0 = __floats2bfloat162_rn((v0.x - mu) * rs * G0.x + B0.x,
                                              (v0.y - mu) * rs * G0.y + B0.y);
    __nv_bfloat162 p1 = __floats2bfloat162_rn((v0.z - mu) * rs * G0.z + B0.z,
                                              (v0.w - mu) * rs * G0.w + B0.w);
    __nv_bfloat162 p2 = __floats2bfloat162_rn((v1.x - mu) * rs * G1.x + B1.x,
                                              (v1.y - mu) * rs * G1.y + B1.y);
    __nv_bfloat162 p3 = __floats2bfloat162_rn((v1.z - mu) * rs * G1.z + B1.z,
                                              (v1.w - mu) * rs * G1.w + B1.w);
    uint2* xo = (uint2*)(g_xnb + row * 256);
    uint2 u0, u1;
    u0.x = *(unsigned*)&p0; u0.y = *(unsigned*)&p1;
    u1.x = *(unsigned*)&p2; u1.y = *(unsigned*)&p3;
    xo[lane] = u0; xo[lane + 32] = u1;
}

// ------------------------------ slot init ----------------------------------
__global__ void __launch_bounds__(256) slots_init_kernel(
    const float* __restrict__ noise_view, const float* __restrict__ noise_attr,
    const float* __restrict__ view_loc, const float* __restrict__ view_log_scl,
    const float* __restrict__ attr_loc, const float* __restrict__ attr_log_scl)
{
    int i = blockIdx.x * 256 + threadIdx.x;
    if (i < BVDIM * SVD) {
        int c = i & 63;
        g_sview[i] = view_loc[c] + expf(view_log_scl[c]) * noise_view[i];
    } else if (i < BVDIM * SVD + 16 * NS * SAD) {
        int j = i - BVDIM * SVD;
        int c = j % SAD;
        g_sattr[j] = attr_loc[c] + expf(attr_log_scl[c]) * noise_attr[j];
    }
}

// ------------------------------ w_hh transpose -----------------------------
// g_whhT[k][j] = w_hh[j][k]   (w_hh is [768][256])
__global__ void __launch_bounds__(256) transpose_whh_kernel(const float* __restrict__ w_hh)
{
    __shared__ float t[32][33];
    int tx = threadIdx.x & 31, ty = threadIdx.x >> 5;
    int j0 = blockIdx.x * 32;   // 24 blocks over j (768)
    int k0 = blockIdx.y * 32;   // 8 blocks over k (256)
    #pragma unroll
    for (int i = 0; i < 4; i++)
        t[ty * 4 + i][tx] = w_hh[(size_t)(j0 + ty * 4 + i) * 256 + k0 + tx];
    __syncthreads();
    #pragma unroll
    for (int i = 0; i < 4; i++)
        g_whhT[(size_t)(k0 + ty * 4 + i) * 768 + j0 + tx] = t[tx][ty * 4 + i];
}

// ------------------------------ generic fp32 GEMM (setup only) -------------
template<bool TRANSB>
__global__ void __launch_bounds__(256) gemm_k(
    int M, int N, int K,
    const float* __restrict__ A, int lda,
    const float* __restrict__ B, int ldb,
    float* __restrict__ C, int ldc, float alpha)
{
    __shared__ float As[16][64];
    __shared__ float Bs[16][64];
    int tid = threadIdx.x;
    int tx = tid & 15, ty = tid >> 4;
    int m0 = blockIdx.y * 64, n0 = blockIdx.x * 64;
    float acc[4][4] = {};
    int ra = tid >> 2, ka = (tid & 3) * 4;
    int kb = tid >> 4, nb = (tid & 15) * 4;
    for (int k0 = 0; k0 < K; k0 += 16) {
        float4 av = *(const float4*)(A + (size_t)(m0 + ra) * lda + k0 + ka);
        As[ka + 0][ra] = av.x; As[ka + 1][ra] = av.y;
        As[ka + 2][ra] = av.z; As[ka + 3][ra] = av.w;
        if (TRANSB) {
            float4 bv = *(const float4*)(B + (size_t)(n0 + ra) * ldb + k0 + ka);
            Bs[ka + 0][ra] = bv.x; Bs[ka + 1][ra] = bv.y;
            Bs[ka + 2][ra] = bv.z; Bs[ka + 3][ra] = bv.w;
        } else {
            float4 bv = *(const float4*)(B + (size_t)(k0 + kb) * ldb + n0 + nb);
            *(float4*)&Bs[kb][nb] = bv;
        }
        __syncthreads();
        #pragma unroll
        for (int kk = 0; kk < 16; kk++) {
            float4 a4 = *(const float4*)&As[kk][ty * 4];
            float4 b4 = *(const float4*)&Bs[kk][tx * 4];
            float ar[4] = {a4.x, a4.y, a4.z, a4.w};
            float br[4] = {b4.x, b4.y, b4.z, b4.w};
            #pragma unroll
            for (int i = 0; i < 4; i++)
                #pragma unroll
                for (int j = 0; j < 4; j++)
                    acc[i][j] += ar[i] * br[j];
        }
        __syncthreads();
    }
    #pragma unroll
    for (int i = 0; i < 4; i++) {
        int row = m0 + ty * 4 + i;
        float4 out;
        out.x = acc[i][0] * alpha; out.y = acc[i][1] * alpha;
        out.z = acc[i][2] * alpha; out.w = acc[i][3] * alpha;
        *(float4*)(C + (size_t)row * ldc + n0 + tx * 4) = out;
    }
}

// ------------------------------ fused pre (per step) -----------------------
// Block = bv (64 blocks). 8 slot rows: build, LN(q), qproj, gh.
__global__ void __launch_bounds__(256) fused_pre_kernel(
    const float* __restrict__ lnqg, const float* __restrict__ lnqb,
    const float* __restrict__ b_hh)
{
    __shared__ float h_s[8][256];
    __shared__ float qln_s[8][256];
    __shared__ float mu_s[8], rs_s[8];
    int bv = blockIdx.x, b = bv >> 2;
    int tid = threadIdx.x, w = tid >> 5, lane = tid & 31;

    #pragma unroll
    for (int r = 0; r < 8; r++) {
        float v = (tid < SVD) ? g_sview[bv * SVD + tid]
                              : g_sattr[(b * 8 + r) * SAD + tid - SVD];
        h_s[r][tid] = v;
        g_h[(bv * 8 + r) * 256 + tid] = v;
    }
    __syncthreads();
    // LN stats: warp w handles row w
    {
        float s = 0.f, ss = 0.f;
        #pragma unroll
        for (int j = 0; j < 8; j++) {
            float v = h_s[w][lane + 32 * j];
            s += v; ss += v * v;
        }
        #pragma unroll
        for (int o = 16; o; o >>= 1) {
            s  += __shfl_xor_sync(0xffffffffu, s, o);
            ss += __shfl_xor_sync(0xffffffffu, ss, o);
        }
        if (lane == 0) {
            float mu = s * (1.f / 256.f);
            mu_s[w] = mu;
            rs_s[w] = rsqrtf(ss * (1.f / 256.f) - mu * mu + 1e-5f);
        }
    }
    __syncthreads();
    {
        float gq = lnqg[tid], bq = lnqb[tid];
        #pragma unroll
        for (int r = 0; r < 8; r++)
            qln_s[r][tid] = (h_s[r][tid] - mu_s[r]) * rs_s[r] * gq + bq;
    }
    __syncthreads();
    // qproj[r][tid] = sum_k qln[r][k] * Mcomb[k][tid]
    {
        float acc[8] = {};
        for (int k = 0; k < 256; k += 4) {
            float w0 = g_Mcomb[(k + 0) * 256 + tid];
            float w1 = g_Mcomb[(k + 1) * 256 + tid];
            float w2 = g_Mcomb[(k + 2) * 256 + tid];
            float w3 = g_Mcomb[(k + 3) * 256 + tid];
            #pragma unroll
            for (int r = 0; r < 8; r++) {
                float4 qv = *(const float4*)&qln_s[r][k];
                acc[r] += qv.x * w0 + qv.y * w1 + qv.z * w2 + qv.w * w3;
            }
        }
        #pragma unroll
        for (int r = 0; r < 8; r++)
            g_qproj[(bv * 8 + r) * 256 + tid] = acc[r];
    }
    // gh[r][j] = sum_k h[r][k] * whhT[k][j] + b_hh[j],  j = tid + 256c
    {
        float acc[3][8] = {};
        for (int k = 0; k < 256; k += 4) {
            float wv[3][4];
            #pragma unroll
            for (int i = 0; i < 4; i++) {
                #pragma unroll
                for (int c = 0; c < 3; c++)
                    wv[c][i] = g_whhT[(size_t)(k + i) * 768 + tid + 256 * c];
            }
            #pragma unroll
            for (int r = 0; r < 8; r++) {
                float4 hv = *(const float4*)&h_s[r][k];
                #pragma unroll
                for (int c = 0; c < 3; c++)
                    acc[c][r] += hv.x * wv[c][0] + hv.y * wv[c][1]
                               + hv.z * wv[c][2] + hv.w * wv[c][3];
            }
        }
        #pragma unroll
        for (int c = 0; c < 3; c++) {
            float bb = b_hh[tid + 256 * c];
            #pragma unroll
            for (int r = 0; r < 8; r++)
                g_gh[(bv * 8 + r) * 768 + tid + 256 * c] = acc[c][r] + bb;
        }
    }
}

// ------------------------------ fused attention ----------------------------
__global__ void __launch_bounds__(256) attn_fused_kernel()
{
    extern __shared__ char smraw[];
    __nv_bfloat16* xs = (__nv_bfloat16*)smraw;            // 64 KB
    float* es = (float*)(smraw + CHUNK * 256 * 2);        // 4 KB
    float* rpart = (float*)(smraw + CHUNK * 256 * 2 + 8 * CHUNK * 4);

    int b = blockIdx.x >> 5;
    int c = blockIdx.x & 31;
    int n0 = c * CHUNK;

    {
        const uint4* src = (const uint4*)(g_xnb + ((size_t)b * NTOK + n0) * 256);
        uint4* dst = (uint4*)xs;
        #pragma unroll
        for (int i = 0; i < 16; i++)
            dst[threadIdx.x + 256 * i] = src[threadIdx.x + 256 * i];
    }

    int w = threadIdx.x >> 5, lane = threadIdx.x & 31;
    // q packed by adjacent slot pairs: qp[sp][j] = (q[2sp], q[2sp+1]) at f=lane+32j
    unsigned long long qp[4][8];
    {
        const float* qb = g_qproj + b * 2048;
        #pragma unroll
        for (int sp = 0; sp < 4; sp++)
            #pragma unroll
            for (int j = 0; j < 8; j++) {
                int f = lane + 32 * j;
                qp[sp][j] = pack2(qb[(2 * sp) * 256 + f], qb[(2 * sp + 1) * 256 + f]);
            }
    }
    __syncthreads();

    // phase 1: raw logits (f32x2), split-tree reduce, store raw l to smem
    #pragma unroll 1
    for (int p = 0; p < 8; p++) {
        int t0 = w * 16 + p * 2;
        const __nv_bfloat16* xp = xs + t0 * 256;
        unsigned long long A0[4], A1[4];
        #pragma unroll
        for (int i = 0; i < 4; i++) { A0[i] = 0ull; A1[i] = 0ull; }
        #pragma unroll
        for (int j = 0; j < 8; j++) {
            float x0 = __bfloat162float(xp[lane + 32 * j]);
            float x1 = __bfloat162float(xp[256 + lane + 32 * j]);
            unsigned long long xx0 = pack2(x0, x0);
            unsigned long long xx1 = pack2(x1, x1);
            #pragma unroll
            for (int sp = 0; sp < 4; sp++) {
                ffma2(A0[sp], xx0, qp[sp][j]);
                ffma2(A1[sp], xx1, qp[sp][j]);
            }
        }
        float a[16];
        #pragma unroll
        for (int sp = 0; sp < 4; sp++) {
            float2 u0 = unpack2(A0[sp]);
            float2 u1 = unpack2(A1[sp]);
            a[2 * sp] = u0.x;     a[2 * sp + 1] = u0.y;
            a[8 + 2 * sp] = u1.x; a[8 + 2 * sp + 1] = u1.y;
        }
        // split-tree reduction
        {
            int k1 = (lane >> 4) & 1;
            #pragma unroll
            for (int i = 0; i < 8; i++) {
                float send = k1 ? a[i] : a[i + 8];
                float recv = __shfl_xor_sync(0xffffffffu, send, 16);
                a[i] = (k1 ? a[i + 8] : a[i]) + recv;
            }
            int k2 = (lane >> 3) & 1;
            #pragma unroll
            for (int i = 0; i < 4; i++) {
                float send = k2 ? a[i] : a[i + 4];
                float recv = __shfl_xor_sync(0xffffffffu, send, 8);
                a[i] = (k2 ? a[i + 4] : a[i]) + recv;
            }
            int k3 = (lane >> 2) & 1;
            #pragma unroll
            for (int i = 0; i < 2; i++) {
                float send = k3 ? a[i] : a[i + 2];
                float recv = __shfl_xor_sync(0xffffffffu, send, 4);
                a[i] = (k3 ? a[i + 2] : a[i]) + recv;
            }
            int k4 = (lane >> 1) & 1;
            {
                float send = k4 ? a[0] : a[1];
                float recv = __shfl_xor_sync(0xffffffffu, send, 2);
                a[0] = (k4 ? a[1] : a[0]) + recv;
            }
            a[0] += __shfl_xor_sync(0xffffffffu, a[0], 1);
        }
        if (!(lane & 1)) {
            int tok = (lane >> 4) & 1;
            int s = ((lane >> 3) & 1) * 4 + ((lane >> 2) & 1) * 2 + ((lane >> 1) & 1);
            es[s * 128 + t0 + tok] = a[0];
        }
    }
    __syncthreads();

    // slot softmax: one thread per token
    if (threadIdx.x < 128) {
        int t = threadIdx.x;
        float l[8];
        #pragma unroll
        for (int s = 0; s < 8; s++) l[s] = es[s * 128 + t];
        float m = l[0];
        #pragma unroll
        for (int s = 1; s < 8; s++) m = fmaxf(m, l[s]);
        float e[8], sum = 0.f;
        #pragma unroll
        for (int s = 0; s < 8; s++) { e[s] = __expf(l[s] - m); sum += e[s]; }
        float inv = __frcp_rn(sum);
        #pragma unroll
        for (int s = 0; s < 8; s++) { e[s] *= inv; es[s * 128 + t] = e[s]; }
        // rowsum partials (split-tree over 8 vals across 32 lanes)
        {
            int k1 = (lane >> 4) & 1;
            #pragma unroll
            for (int i = 0; i < 4; i++) {
                float send = k1 ? e[i] : e[i + 4];
                float recv = __shfl_xor_sync(0xffffffffu, send, 16);
                e[i] = (k1 ? e[i + 4] : e[i]) + recv;
            }
            int k2 = (lane >> 3) & 1;
            #pragma unroll
            for (int i = 0; i < 2; i++) {
                float send = k2 ? e[i] : e[i + 2];
                float recv = __shfl_xor_sync(0xffffffffu, send, 8);
                e[i] = (k2 ? e[i + 2] : e[i]) + recv;
            }
            int k3 = (lane >> 2) & 1;
            {
                float send = k3 ? e[0] : e[1];
                float recv = __shfl_xor_sync(0xffffffffu, send, 4);
                e[0] = (k3 ? e[1] : e[0]) + recv;
            }
            e[0] += __shfl_xor_sync(0xffffffffu, e[0], 2);
            e[0] += __shfl_xor_sync(0xffffffffu, e[0], 1);
            if (!(lane & 3)) {
                int s = ((lane >> 4) & 1) * 4 + ((lane >> 3) & 1) * 2 + ((lane >> 2) & 1);
                rpart[(t >> 5) * 8 + s] = e[0];
            }
        }
    }
    __syncthreads();
    if (threadIdx.x < 8)
        g_rspart[c * ROWS + b * 8 + threadIdx.x] =
            rpart[threadIdx.x] + rpart[8 + threadIdx.x] +
            rpart[16 + threadIdx.x] + rpart[24 + threadIdx.x];

    // phase 2: upart[s][f] = sum_t e[s][t]*x[t][f] with f32x2
    int f = threadIdx.x;
    unsigned long long acc2[8];
    #pragma unroll
    for (int s = 0; s < 8; s++) acc2[s] = 0ull;
    #pragma unroll 2
    for (int t = 0; t < 128; t += 4) {
        float x0 = __bfloat162float(xs[(t + 0) * 256 + f]);
        float x1 = __bfloat162float(xs[(t + 1) * 256 + f]);
        float x2 = __bfloat162float(xs[(t + 2) * 256 + f]);
        float x3 = __bfloat162float(xs[(t + 3) * 256 + f]);
        unsigned long long p01 = pack2(x0, x1);
        unsigned long long p23 = pack2(x2, x3);
        #pragma unroll
        for (int s = 0; s < 8; s++) {
            ulonglong2 ev = *(const ulonglong2*)&es[s * 128 + t];
            ffma2(acc2[s], ev.x, p01);
            ffma2(acc2[s], ev.y, p23);
        }
    }
    #pragma unroll
    for (int s = 0; s < 8; s++) {
        float2 u = unpack2(acc2[s]);
        g_upart[((size_t)c * ROWS + b * 8 + s) * 256 + f] = u.x + u.y;
    }
}

// ------------------------------ fused post (per step) ----------------------
// Block = bv. ureduce + gi + GRU + LN + t1 + snew + slot_view mean.
__global__ void __launch_bounds__(256) fused_post_kernel(
    const float* __restrict__ b_ih,
    const float* __restrict__ lnrg, const float* __restrict__ lnrb,
    const float* __restrict__ W_r1, const float* __restrict__ b_r1,
    const float* __restrict__ W_r2, const float* __restrict__ b_r2)
{
    __shared__ float upre_s[8][256];
    __shared__ float xm_s[8][256];
    __shared__ float rln_s[8][256];
    __shared__ float t1_s[8][512];
    __shared__ float mu_s[8], rs_s[8], rsum_s[8];
    int bv = blockIdx.x;
    int tid = threadIdx.x, w = tid >> 5, lane = tid & 31;

    if (tid < 8) {
        float rs = 0.f;
        #pragma unroll
        for (int c = 0; c < NCHUNK; c++) rs += g_rspart[c * ROWS + bv * 8 + tid];
        rsum_s[tid] = rs;
    }
    __syncthreads();
    #pragma unroll
    for (int r = 0; r < 8; r++) {
        float s = 0.f;
        #pragma unroll 8
        for (int c = 0; c < NCHUNK; c++)
            s += g_upart[((size_t)c * ROWS + bv * 8 + r) * 256 + tid];
        upre_s[r][tid] = s / rsum_s[r];
    }
    __syncthreads();

    // gi[c][r] = sum_k upre[r][k] * Mvih[k][tid+256c]
    float gi[3][8] = {};
    for (int k = 0; k < 256; k += 4) {
        float wv[3][4];
        #pragma unroll
        for (int i = 0; i < 4; i++) {
            #pragma unroll
            for (int c = 0; c < 3; c++)
                wv[c][i] = g_Mvih[(size_t)(k + i) * 768 + tid + 256 * c];
        }
        #pragma unroll
        for (int r = 0; r < 8; r++) {
            float4 uv = *(const float4*)&upre_s[r][k];
            #pragma unroll
            for (int c = 0; c < 3; c++)
                gi[c][r] += uv.x * wv[c][0] + uv.y * wv[c][1]
                          + uv.z * wv[c][2] + uv.w * wv[c][3];
        }
    }

    // GRU
    float bi0 = b_ih[tid], bi1 = b_ih[tid + 256], bi2 = b_ih[tid + 512];
    float xm[8];
    #pragma unroll
    for (int r = 0; r < 8; r++) {
        int row = bv * 8 + r;
        float gh0 = g_gh[row * 768 + tid];
        float gh1 = g_gh[row * 768 + 256 + tid];
        float gh2 = g_gh[row * 768 + 512 + tid];
        float rg = sigmoidf(gi[0][r] + bi0 + gh0);
        float z  = sigmoidf(gi[1][r] + bi1 + gh1);
        float nn = tanhf(gi[2][r] + bi2 + rg * gh2);
        float hv = g_h[row * 256 + tid];
        xm[r] = (1.f - z) * nn + z * hv;
        xm_s[r][tid] = xm[r];
    }
    __syncthreads();
    // LN stats: warp w row w
    {
        float s = 0.f, ss = 0.f;
        #pragma unroll
        for (int j = 0; j < 8; j++) {
            float v = xm_s[w][lane + 32 * j];
            s += v; ss += v * v;
        }
        #pragma unroll
        for (int o = 16; o; o >>= 1) {
            s  += __shfl_xor_sync(0xffffffffu, s, o);
            ss += __shfl_xor_sync(0xffffffffu, ss, o);
        }
        if (lane == 0) {
            float mu = s * (1.f / 256.f);
            mu_s[w] = mu;
            rs_s[w] = rsqrtf(ss * (1.f / 256.f) - mu * mu + 1e-5f);
        }
    }
    __syncthreads();
    {
        float gr = lnrg[tid], br = lnrb[tid];
        #pragma unroll
        for (int r = 0; r < 8; r++)
            rln_s[r][tid] = (xm[r] - mu_s[r]) * rs_s[r] * gr + br;
    }
    __syncthreads();

    // t1[c][r] = relu(sum_k rln[r][k]*W_r1[k][tid+256c] + b_r1)
    {
        float acc[2][8] = {};
        for (int k = 0; k < 256; k += 4) {
            float wv[2][4];
            #pragma unroll
            for (int i = 0; i < 4; i++) {
                #pragma unroll
                for (int c = 0; c < 2; c++)
                    wv[c][i] = W_r1[(size_t)(k + i) * 512 + tid + 256 * c];
            }
            #pragma unroll
            for (int r = 0; r < 8; r++) {
                float4 rv = *(const float4*)&rln_s[r][k];
                #pragma unroll
                for (int c = 0; c < 2; c++)
                    acc[c][r] += rv.x * wv[c][0] + rv.y * wv[c][1]
                               + rv.z * wv[c][2] + rv.w * wv[c][3];
            }
        }
        #pragma unroll
        for (int c = 0; c < 2; c++) {
            float bb = b_r1[tid + 256 * c];
            #pragma unroll
            for (int r = 0; r < 8; r++)
                t1_s[r][tid + 256 * c] = fmaxf(acc[c][r] + bb, 0.f);
        }
    }
    __syncthreads();

    // snew[r][tid] = xm + sum_k t1[r][k]*W_r2[k][tid] + b_r2
    {
        float out[8] = {};
        for (int k = 0; k < 512; k += 4) {
            float w0 = W_r2[(size_t)(k + 0) * 256 + tid];
            float w1 = W_r2[(size_t)(k + 1) * 256 + tid];
            float w2 = W_r2[(size_t)(k + 2) * 256 + tid];
            float w3 = W_r2[(size_t)(k + 3) * 256 + tid];
            #pragma unroll
            for (int r = 0; r < 8; r++) {
                float4 tv = *(const float4*)&t1_s[r][k];
                out[r] += tv.x * w0 + tv.y * w1 + tv.z * w2 + tv.w * w3;
            }
        }
        float b2 = b_r2[tid];
        #pragma unroll
        for (int r = 0; r < 8; r++) {
            float v = out[r] + b2 + xm[r];
            g_snew[(bv * 8 + r) * 256 + tid] = v;
            out[r] = v;
        }
        // slot_view mean (cols < 64, all 8 slots local to this block)
        if (tid < SVD) {
            float s = 0.f;
            #pragma unroll
            for (int r = 0; r < 8; r++) s += out[r];
            g_sview[bv * SVD + tid] = s * 0.125f;
        }
    }
}

// ------------------------------ slot_attr means ----------------------------
__global__ void __launch_bounds__(256) means_attr_kernel()
{
    int j = blockIdx.x * 256 + threadIdx.x;     // 16*8*192 = 24576
    if (j >= 16 * NS * SAD) return;
    int bs = j / SAD, c = j % SAD;
    int b = bs >> 3, s = bs & 7;
    float t = 0.f;
    #pragma unroll
    for (int v = 0; v < 4; v++)
        t += g_snew[((b * 4 + v) * 8 + s) * 256 + SVD + c];
    g_sattr[j] = t * 0.25f;
}

// ------------------------------ output copy --------------------------------
__global__ void __launch_bounds__(256) copy_out_kernel(float* __restrict__ out, int out_size)
{
    int i = blockIdx.x * 256 + threadIdx.x;
    if (i >= out_size) return;
    if (i < BVDIM * SVD) out[i] = g_sview[i];
    else out[i] = g_sattr[i - BVDIM * SVD];
}

// ------------------------------ host side ----------------------------------
template <typename T>
static float* sym_addr(const T& sym) {
    void* p = nullptr;
    cudaGetSymbolAddress(&p, sym);
    return (float*)p;
}

extern "C" void kernel_launch(void* const* d_in, const int* in_sizes, int n_in,
                              void* d_out, int out_size)
{
    const float* x             = (const float*)d_in[0];
    const float* noise_view    = (const float*)d_in[1];
    const float* noise_attr    = (const float*)d_in[2];
    const float* view_loc      = (const float*)d_in[3];
    const float* view_log_scl  = (const float*)d_in[4];
    const float* attr_loc      = (const float*)d_in[5];
    const float* attr_log_scl  = (const float*)d_in[6];
    const float* ln_kv_g       = (const float*)d_in[7];
    const float* ln_kv_b       = (const float*)d_in[8];
    const float* W_kv          = (const float*)d_in[9];
    const float* ln_q_g        = (const float*)d_in[10];
    const float* ln_q_b        = (const float*)d_in[11];
    const float* W_qry         = (const float*)d_in[12];
    const float* w_ih          = (const float*)d_in[13];
    const float* w_hh          = (const float*)d_in[14];
    const float* b_ih          = (const float*)d_in[15];
    const float* b_hh          = (const float*)d_in[16];
    const float* ln_r_g        = (const float*)d_in[17];
    const float* ln_r_b        = (const float*)d_in[18];
    const float* W_r1          = (const float*)d_in[19];
    const float* b_r1          = (const float*)d_in[20];
    const float* W_r2          = (const float*)d_in[21];
    const float* b_r2          = (const float*)d_in[22];

    float* pMcomb = sym_addr(g_Mcomb);
    float* pMvih  = sym_addr(g_Mvih);

    const int attn_smem = CHUNK * 256 * 2 + 8 * CHUNK * 4 + 32 * 4;
    static bool attr_set = false;
    if (!attr_set) {
        cudaFuncSetAttribute(attn_fused_kernel,
                             cudaFuncAttributeMaxDynamicSharedMemorySize, attn_smem);
        attr_set = true;
    }

    // setup
    ln_x_kernel<<<32768, 256>>>(x, ln_kv_g, ln_kv_b);
    slots_init_kernel<<<112, 256>>>(noise_view, noise_attr, view_loc, view_log_scl,
                                    attr_loc, attr_log_scl);
    // M_comb = coef * W_qry @ W_k^T   (W_k = W_kv[:, :128])
    gemm_k<true><<<dim3(4, 4), 256>>>(256, 256, 128, W_qry, 128, W_kv, 384,
                                      pMcomb, 256, COEF);
    // M_vih = W_v @ w_ih^T            (W_v = W_kv[:, 128:384])
    gemm_k<true><<<dim3(12, 4), 256>>>(256, 768, 256, W_kv + 128, 384, w_ih, 256,
                                       pMvih, 768, 1.f);
    transpose_whh_kernel<<<dim3(24, 8), 256>>>(w_hh);

    for (int step = 0; step < 3; step++) {
        fused_pre_kernel<<<BVDIM, 256>>>(ln_q_g, ln_q_b, b_hh);
        attn_fused_kernel<<<BVDIM * NCHUNK, 256, attn_smem>>>();
        fused_post_kernel<<<BVDIM, 256>>>(b_ih, ln_r_g, ln_r_b, W_r1, b_r1, W_r2, b_r2);
        means_attr_kernel<<<96, 256>>>();
    }

    copy_out_kernel<<<(out_size + 255) / 256, 256>>>((float*)d_out, out_size);
}